// round 17
// baseline (speedup 1.0000x reference)
#include <cuda_runtime.h>
#include <cuda_fp16.h>
#include <cstdint>

#define XP 136
#define AP 136
#define CP 136

struct Sm {
    __half xhi[3][128 * XP];
    __half chi[32 * CP];
    __half ahi[2][32 * AP];
    float x2[3][128];
    float x2p[512];
    float Spart[8 * 32];
    float c2[32], scl[32];
};

static __device__ __forceinline__ uint32_t sptr(const void* p) {
    return (uint32_t)__cvta_generic_to_shared(p);
}
static __device__ __forceinline__ void ldsm4(uint32_t* r, uint32_t a) {
    asm volatile("ldmatrix.sync.aligned.m8n8.x4.shared.b16 {%0,%1,%2,%3},[%4];"
                 : "=r"(r[0]), "=r"(r[1]), "=r"(r[2]), "=r"(r[3]) : "r"(a));
}
static __device__ __forceinline__ void ldsm4t(uint32_t* r, uint32_t a) {
    asm volatile("ldmatrix.sync.aligned.m8n8.x4.trans.shared.b16 {%0,%1,%2,%3},[%4];"
                 : "=r"(r[0]), "=r"(r[1]), "=r"(r[2]), "=r"(r[3]) : "r"(a));
}
static __device__ __forceinline__ void mma16816(float* c, const uint32_t* a, const uint32_t* b) {
    asm volatile(
        "mma.sync.aligned.m16n8k16.row.col.f32.f16.f16.f32 "
        "{%0,%1,%2,%3},{%4,%5,%6,%7},{%8,%9},{%0,%1,%2,%3};"
        : "+f"(c[0]), "+f"(c[1]), "+f"(c[2]), "+f"(c[3])
        : "r"(a[0]), "r"(a[1]), "r"(a[2]), "r"(a[3]), "r"(b[0]), "r"(b[1]));
}
static __device__ __forceinline__ void barsync(int id, int cnt) {
    asm volatile("bar.sync %0, %1;" :: "r"(id), "r"(cnt) : "memory");
}
static __device__ __forceinline__ void bararrive(int id, int cnt) {
    asm volatile("bar.arrive %0, %1;" :: "r"(id), "r"(cnt) : "memory");
}

// bars: FULL s=1+s (384: prod128+sm256) ; EMPTY s=4+s (512: sm256+g2 128+prod128)
//       barA p=7+p (384: sm256 arrive + g2 128 sync) ; AEMPTY p=9+p (384: g2 arrive + sm sync)
//       prod internal = 11 (128)

__global__ void __launch_bounds__(512, 1)
enc_kernel(const float* __restrict__ X, const float* __restrict__ Cg,
           const float* __restrict__ scaleg, float* __restrict__ out)
{
    extern __shared__ char raw[];
    Sm& s = *reinterpret_cast<Sm*>(raw);
    const int tid = threadIdx.x, lane = tid & 31, w = tid >> 5;

    for (int i = tid; i < 4096; i += 512) {
        int k = i >> 7, d = i & 127;
        s.chi[k * CP + d] = __float2half(Cg[i]);
    }
    if (tid < 32) {
        float c2 = 0.f;
        #pragma unroll 8
        for (int d = 0; d < 128; d++) { float c = Cg[tid * 128 + d]; c2 += c * c; }
        s.c2[tid] = c2;
        s.scl[tid] = scaleg[tid];
    }
    __syncthreads();

    const int nq = (1024 - (int)blockIdx.x + (int)gridDim.x - 1) / (int)gridDim.x;
    const int TL = nq * 4;
    const int g = lane >> 2, t = lane & 3;
    const int lr = lane & 15, lh = lane >> 4;

    if (w >= 12) {
        // ===== PRODUCER (warps 12-15, highest wid): 32 rows each, 8-row batches =====
        const int pw = w - 12;
        const int nl = lane * 4;
        const int r0 = pw * 32;
        float4 va[8], vb[8];
        {
            const int u = blockIdx.x;
            const float* base = X + (size_t)(u >> 5) * (128 * 16384) + (u & 31) * 512 + nl;
            #pragma unroll
            for (int i = 0; i < 8; i++)
                va[i] = *reinterpret_cast<const float4*>(base + (size_t)(r0 + i) * 16384);
        }
        int bi = 0;
        for (int tl = 0; tl < TL; tl++) {
            const int u = blockIdx.x + (tl >> 2) * gridDim.x;
            const float* base = X + (size_t)(u >> 5) * (128 * 16384)
                              + (u & 31) * 512 + (tl & 3) * 128 + nl;
            barsync(4 + bi, 512);
            __half* xh = s.xhi[bi];
            float p0 = 0.f, p1 = 0.f, p2 = 0.f, p3 = 0.f;
            #pragma unroll
            for (int seg = 0; seg < 4; seg++) {
                float4* cur = (seg & 1) ? vb : va;
                float4* nxt = (seg & 1) ? va : vb;
                if (seg < 3) {
                    #pragma unroll
                    for (int i = 0; i < 8; i++)
                        nxt[i] = *reinterpret_cast<const float4*>(
                            base + (size_t)(r0 + (seg + 1) * 8 + i) * 16384);
                }
                #pragma unroll
                for (int i = 0; i < 8; i++) {
                    const int d = r0 + seg * 8 + i;
                    const float4 v = cur[i];
                    __half2 H0 = __floats2half2_rn(v.x, v.y);
                    __half2 H1 = __floats2half2_rn(v.z, v.w);
                    uint2 pk;
                    pk.x = *reinterpret_cast<uint32_t*>(&H0);
                    pk.y = *reinterpret_cast<uint32_t*>(&H1);
                    *reinterpret_cast<uint2*>(&xh[d * XP + nl]) = pk;
                    p0 = fmaf(v.x, v.x, p0); p1 = fmaf(v.y, v.y, p1);
                    p2 = fmaf(v.z, v.z, p2); p3 = fmaf(v.w, v.w, p3);
                }
            }
            *reinterpret_cast<float4*>(&s.x2p[pw * 128 + nl]) = make_float4(p0, p1, p2, p3);
            barsync(11, 128);
            {
                const int pr = tid - 384;
                float sum = s.x2p[pr] + s.x2p[128 + pr] + s.x2p[256 + pr] + s.x2p[384 + pr];
                s.x2[bi][pr] = sum;
            }
            __threadfence_block();
            bararrive(1 + bi, 384);
            if (tl + 1 < TL) {
                const int u2 = blockIdx.x + ((tl + 1) >> 2) * gridDim.x;
                const float* b2 = X + (size_t)(u2 >> 5) * (128 * 16384)
                                + (u2 & 31) * 512 + ((tl + 1) & 3) * 128 + nl;
                #pragma unroll
                for (int i = 0; i < 8; i++)
                    va[i] = *reinterpret_cast<const float4*>(b2 + (size_t)(r0 + i) * 16384);
            }
            bi = (bi == 2) ? 0 : bi + 1;
        }
    } else if (w < 8) {
        // ===== SOFTMAX warps (0-7): GEMM1 + softmax + A-write, 16n each =====
        const int nb = w * 16;
        const float sc0 = s.scl[g],      cc0 = s.c2[g];
        const float sc1 = s.scl[g + 8],  cc1 = s.c2[g + 8];
        const float sc2 = s.scl[g + 16], cc2 = s.c2[g + 16];
        const float sc3 = s.scl[g + 24], cc3 = s.c2[g + 24];
        uint32_t cfr[2][2][4];
        #pragma unroll
        for (int kd = 0; kd < 2; kd++) {
            ldsm4(cfr[kd][0], sptr(&s.chi[lr * CP + kd * 16 + lh * 8]));
            ldsm4(cfr[kd][1], sptr(&s.chi[(16 + lr) * CP + kd * 16 + lh * 8]));
        }
        bararrive(4, 512); bararrive(5, 512); bararrive(6, 512);
        float Sr[4] = {0.f, 0.f, 0.f, 0.f};

        for (int tl = 0; tl < TL; tl++) {
            const int bi = tl % 3, pa = tl & 1;
            barsync(1 + bi, 384);                    // X full
            const __half* xh = s.xhi[bi];

            float acc[2][2][4];
            #pragma unroll
            for (int mt = 0; mt < 2; mt++)
                #pragma unroll
                for (int nt = 0; nt < 2; nt++) {
                    acc[mt][nt][0] = 0.f; acc[mt][nt][1] = 0.f;
                    acc[mt][nt][2] = 0.f; acc[mt][nt][3] = 0.f;
                }
            #pragma unroll
            for (int kd = 0; kd < 2; kd++) {
                uint32_t bh[4];
                ldsm4t(bh, sptr(&xh[(kd * 16 + lr) * XP + nb + lh * 8]));
                mma16816(acc[0][0], cfr[kd][0], bh + 0);
                mma16816(acc[0][1], cfr[kd][0], bh + 2);
                mma16816(acc[1][0], cfr[kd][1], bh + 0);
                mma16816(acc[1][1], cfr[kd][1], bh + 2);
            }
            #pragma unroll
            for (int kd = 2; kd < 8; kd++) {
                uint32_t a0[4], a1[4], bh[4];
                ldsm4(a0, sptr(&s.chi[lr * CP + kd * 16 + lh * 8]));
                ldsm4(a1, sptr(&s.chi[(16 + lr) * CP + kd * 16 + lh * 8]));
                ldsm4t(bh, sptr(&xh[(kd * 16 + lr) * XP + nb + lh * 8]));
                mma16816(acc[0][0], a0, bh + 0);
                mma16816(acc[0][1], a0, bh + 2);
                mma16816(acc[1][0], a1, bh + 0);
                mma16816(acc[1][1], a1, bh + 2);
            }
            // x2 read precedes EMPTY arrive (producer refill gated by gemm2 anyway,
            // but keep strict order: read x2 now)
            const float* x2 = s.x2[bi];
            float sl[4][4], m[4], sum[4];
            #pragma unroll
            for (int j = 0; j < 4; j++) {
                const int nt = j >> 1, jc = j & 1;
                const float xv = x2[nb + nt * 8 + 2 * t + jc];
                sl[j][0] = sc0 * (xv - 2.f * acc[0][nt][jc]     + cc0);
                sl[j][1] = sc1 * (xv - 2.f * acc[0][nt][jc + 2] + cc1);
                sl[j][2] = sc2 * (xv - 2.f * acc[1][nt][jc]     + cc2);
                sl[j][3] = sc3 * (xv - 2.f * acc[1][nt][jc + 2] + cc3);
                m[j] = fmaxf(fmaxf(sl[j][0], sl[j][1]), fmaxf(sl[j][2], sl[j][3]));
            }
            bararrive(4 + bi, 512);                  // softmax done with X buffer
            #pragma unroll
            for (int j = 0; j < 4; j++) {
                m[j] = fmaxf(m[j], __shfl_xor_sync(0xffffffffu, m[j], 4));
                m[j] = fmaxf(m[j], __shfl_xor_sync(0xffffffffu, m[j], 8));
                m[j] = fmaxf(m[j], __shfl_xor_sync(0xffffffffu, m[j], 16));
                sl[j][0] = __expf(sl[j][0] - m[j]); sl[j][1] = __expf(sl[j][1] - m[j]);
                sl[j][2] = __expf(sl[j][2] - m[j]); sl[j][3] = __expf(sl[j][3] - m[j]);
                sum[j] = sl[j][0] + sl[j][1] + sl[j][2] + sl[j][3];
                sum[j] += __shfl_xor_sync(0xffffffffu, sum[j], 4);
                sum[j] += __shfl_xor_sync(0xffffffffu, sum[j], 8);
                sum[j] += __shfl_xor_sync(0xffffffffu, sum[j], 16);
                const float f = 1.f / sum[j];
                sl[j][0] *= f; sl[j][1] *= f; sl[j][2] *= f; sl[j][3] *= f;
                Sr[0] += sl[j][0]; Sr[1] += sl[j][1];
                Sr[2] += sl[j][2]; Sr[3] += sl[j][3];
            }
            barsync(9 + pa, 384);                    // A buffer pa free (gemm2 done)
            __half* ac = s.ahi[pa];
            #pragma unroll
            for (int i = 0; i < 4; i++) {
                const int k = (i < 2) ? (g + 8 * i) : (16 + g + 8 * (i - 2));
                #pragma unroll
                for (int jp = 0; jp < 2; jp++) {
                    __half2 H = __floats2half2_rn(sl[jp * 2 + 0][i], sl[jp * 2 + 1][i]);
                    *reinterpret_cast<__half2*>(&ac[k * AP + nb + jp * 8 + 2 * t]) = H;
                }
            }
            if ((tl & 3) == 3) {
                #pragma unroll
                for (int o = 1; o <= 2; o <<= 1) {
                    Sr[0] += __shfl_xor_sync(0xffffffffu, Sr[0], o);
                    Sr[1] += __shfl_xor_sync(0xffffffffu, Sr[1], o);
                    Sr[2] += __shfl_xor_sync(0xffffffffu, Sr[2], o);
                    Sr[3] += __shfl_xor_sync(0xffffffffu, Sr[3], o);
                }
                if (t == 0) {
                    s.Spart[w * 32 + g]      = Sr[0];
                    s.Spart[w * 32 + g + 8]  = Sr[1];
                    s.Spart[w * 32 + g + 16] = Sr[2];
                    s.Spart[w * 32 + g + 24] = Sr[3];
                }
                Sr[0] = 0.f; Sr[1] = 0.f; Sr[2] = 0.f; Sr[3] = 0.f;
            }
            __threadfence_block();
            bararrive(7 + pa, 384);                  // A(tl) + Spart ready
        }
    } else {
        // ===== GEMM2 warps (8-11): 32 d-rows each, lag behind softmax by design =====
        const int hw2 = w - 8;
        const int brow = (lane >> 4) * 8 + (lane & 7);
        const int bcol = ((lane >> 3) & 1) * 8;
        bararrive(4, 512); bararrive(5, 512); bararrive(6, 512);
        bararrive(9, 384); bararrive(10, 384);
        float e[2][4][4];
        #pragma unroll
        for (int dt = 0; dt < 2; dt++)
            #pragma unroll
            for (int j = 0; j < 4; j++) {
                e[dt][j][0] = 0.f; e[dt][j][1] = 0.f;
                e[dt][j][2] = 0.f; e[dt][j][3] = 0.f;
            }

        for (int tl = 0; tl < TL; tl++) {
            const int bi = tl % 3, pa = tl & 1;
            barsync(7 + pa, 384);                    // A(tl) ready
            const __half* xh = s.xhi[bi];
            const __half* ap = s.ahi[pa];
            #pragma unroll
            for (int kn = 0; kn < 8; kn++) {
                const int nn = kn * 16;
                uint32_t X0[4], X1[4], b0h[4], b1h[4];
                ldsm4(X0, sptr(&xh[(hw2 * 32 + lr) * XP + nn + lh * 8]));
                ldsm4(X1, sptr(&xh[(hw2 * 32 + 16 + lr) * XP + nn + lh * 8]));
                ldsm4(b0h, sptr(&ap[brow * AP + nn + bcol]));
                ldsm4(b1h, sptr(&ap[(16 + brow) * AP + nn + bcol]));
                mma16816(e[0][0], X0, b0h + 0);
                mma16816(e[0][1], X0, b0h + 2);
                mma16816(e[0][2], X0, b1h + 0);
                mma16816(e[0][3], X0, b1h + 2);
                mma16816(e[1][0], X1, b0h + 0);
                mma16816(e[1][1], X1, b0h + 2);
                mma16816(e[1][2], X1, b1h + 0);
                mma16816(e[1][3], X1, b1h + 2);
            }
            if ((tl & 3) == 3) {
                const int uf = blockIdx.x + (tl >> 2) * gridDim.x;
                float* outb = out + (size_t)(uf >> 5) * 4096;
                #pragma unroll
                for (int j = 0; j < 4; j++) {
                    const int k0 = j * 8 + 2 * t;
                    float S0 = 0.f, S1 = 0.f;
                    #pragma unroll
                    for (int q = 0; q < 8; q++) {
                        S0 += s.Spart[q * 32 + k0];
                        S1 += s.Spart[q * 32 + k0 + 1];
                    }
                    #pragma unroll
                    for (int dt = 0; dt < 2; dt++) {
                        const int d0 = hw2 * 32 + dt * 16 + g;
                        atomicAdd(&outb[k0 * 128 + d0],           e[dt][j][0] - S0 * Cg[k0 * 128 + d0]);
                        atomicAdd(&outb[(k0 + 1) * 128 + d0],     e[dt][j][1] - S1 * Cg[(k0 + 1) * 128 + d0]);
                        atomicAdd(&outb[k0 * 128 + d0 + 8],       e[dt][j][2] - S0 * Cg[k0 * 128 + d0 + 8]);
                        atomicAdd(&outb[(k0 + 1) * 128 + d0 + 8], e[dt][j][3] - S1 * Cg[(k0 + 1) * 128 + d0 + 8]);
                        e[dt][j][0] = 0.f; e[dt][j][1] = 0.f;
                        e[dt][j][2] = 0.f; e[dt][j][3] = 0.f;
                    }
                }
            }
            bararrive(9 + pa, 384);                  // A buffer free
            bararrive(4 + bi, 512);                  // X buffer free
        }
    }
}

extern "C" void kernel_launch(void* const* d_in, const int* in_sizes, int n_in,
                              void* d_out, int out_size) {
    const float* X  = (const float*)d_in[0];
    const float* C  = (const float*)d_in[1];
    const float* sc = (const float*)d_in[2];
    float* out = (float*)d_out;

    int dev = 0, sms = 0;
    cudaGetDevice(&dev);
    cudaDeviceGetAttribute(&sms, cudaDevAttrMultiProcessorCount, dev);
    if (sms <= 0) sms = 148;

    cudaFuncSetAttribute(enc_kernel, cudaFuncAttributeMaxDynamicSharedMemorySize,
                         (int)sizeof(Sm));
    cudaMemsetAsync(out, 0, (size_t)out_size * sizeof(float));
    enc_kernel<<<sms, 512, sizeof(Sm)>>>(X, C, sc, out);
}